// round 9
// baseline (speedup 1.0000x reference)
#include <cuda_runtime.h>
#include <cstdint>

#define EE 256
#define HN 8
#define DH 32
#define LLAYERS 4
#define FFD 1024
#define NQ 64
#define PAIRS 2016
#define PPAD 2048
#define MMEM 4096
#define TTXT 32

// ---------------- scratch (static device globals; allocation-free) ----------------
__device__ float g_q[PPAD * EE];
__device__ float g_qh[PPAD * EE];
__device__ float g_kall[LLAYERS * MMEM * EE];
__device__ float g_vall[LLAYERS * MMEM * EE];
__device__ float g_proj[PPAD * EE];
__device__ float g_text[TTXT * EE];
__device__ int   g_rowi[PAIRS];
__device__ int   g_coli[PAIRS];
__device__ float g_refx[PAIRS];
__device__ float g_refy[PAIRS];

// packed weights (hi/lo bf16x2 over k-pairs): WH[k2][n]
__device__ uint32_t g_WpairH[256 * 256], g_WpairL[256 * 256];
__device__ uint32_t g_WmemH[128 * 256],  g_WmemL[128 * 256];
__device__ uint32_t g_WtextH[128 * 256], g_WtextL[128 * 256];
__device__ uint32_t g_WqH[LLAYERS * 128 * 256], g_WqL[LLAYERS * 128 * 256];
__device__ uint32_t g_WkH[LLAYERS * 128 * 256], g_WkL[LLAYERS * 128 * 256];
__device__ uint32_t g_WvH[LLAYERS * 128 * 256], g_WvL[LLAYERS * 128 * 256];
__device__ uint32_t g_WoH[LLAYERS * 128 * 256], g_WoL[LLAYERS * 128 * 256];
__device__ uint32_t g_Wf1H[LLAYERS * 128 * 1024], g_Wf1L[LLAYERS * 128 * 1024];
__device__ uint32_t g_Wf2H[LLAYERS * 512 * 256],  g_Wf2L[LLAYERS * 512 * 256];
// packed activations: AH[m][k2]
__device__ uint32_t g_pcH[PPAD * 256],  g_pcL[PPAD * 256];
__device__ uint32_t g_qPH[PPAD * 128],  g_qPL[PPAD * 128];
__device__ uint32_t g_minH[MMEM * 128], g_minL[MMEM * 128];
__device__ uint32_t g_mtxH[TTXT * 128], g_mtxL[TTXT * 128];
__device__ uint32_t g_memH[MMEM * 128], g_memL[MMEM * 128];
__device__ uint32_t g_atH[PPAD * 128],  g_atL[PPAD * 128];
__device__ uint32_t g_ffH[PPAD * 512],  g_ffL[PPAD * 512];

__device__ __forceinline__ void mma_bf16(float* c, uint32_t a0, uint32_t a1,
                                         uint32_t a2, uint32_t a3,
                                         uint32_t b0, uint32_t b1) {
    asm volatile(
        "mma.sync.aligned.m16n8k16.row.col.f32.bf16.bf16.f32 "
        "{%0,%1,%2,%3}, {%4,%5,%6,%7}, {%8,%9}, {%0,%1,%2,%3};\n"
        : "+f"(c[0]), "+f"(c[1]), "+f"(c[2]), "+f"(c[3])
        : "r"(a0), "r"(a1), "r"(a2), "r"(a3), "r"(b0), "r"(b1));
}

__device__ __forceinline__ uint32_t pack_bf2(float e_lo, float e_hi) {
    uint32_t r;
    asm("cvt.rn.bf16x2.f32 %0, %1, %2;" : "=r"(r) : "f"(e_hi), "f"(e_lo));
    return r;
}
__device__ __forceinline__ float bf_lo(uint32_t p) { return __uint_as_float(p << 16); }
__device__ __forceinline__ float bf_hi(uint32_t p) { return __uint_as_float(p & 0xffff0000u); }
__device__ __forceinline__ void split2(float a, float b, uint32_t& h, uint32_t& l) {
    h = pack_bf2(a, b);
    l = pack_bf2(a - bf_lo(h), b - bf_hi(h));
}

// ---------------- pack kernels -----------------------------------------------------
// weights: src[l][K][N] -> H/L[l][K/2][N], pairing rows (N apart)
__global__ void pack_w(const float* __restrict__ src, uint32_t* __restrict__ H,
                       uint32_t* __restrict__ L, int K, int N, int total) {
    int g = blockIdx.x * 256 + threadIdx.x;
    if (g >= total) return;
    int half = (K >> 1) * N;
    int l = g / half, r = g % half;
    int k2 = r / N, n = r % N;
    const float* s = src + (size_t)l * K * N;
    float a = s[(size_t)(2 * k2) * N + n], b = s[(size_t)(2 * k2 + 1) * N + n];
    split2(a, b, H[g], L[g]);
}
// activations row-major: adjacent element pairs = flat pairs
__global__ void pack_a(const float* __restrict__ src, uint32_t* __restrict__ H,
                       uint32_t* __restrict__ L, int n2) {
    int g = blockIdx.x * 256 + threadIdx.x;
    if (g >= n2) return;
    float2 v = *(const float2*)(src + 2 * (size_t)g);
    split2(v.x, v.y, H[g], L[g]);
}

// ---------------- packed-operand bf16x2 3-product GEMM ----------------------------
// block 64x64, BK=32, 128 thr (4 warps), warp tile 32x32.
template <bool RELU, bool PACKOUT>
__device__ __forceinline__ void gemm_pk_body(const uint32_t* __restrict__ AH,
                                             const uint32_t* __restrict__ AL,
                                             const uint32_t* __restrict__ BH,
                                             const uint32_t* __restrict__ BL,
                                             const float* __restrict__ bias,
                                             float* __restrict__ C,
                                             uint32_t* __restrict__ CH,
                                             uint32_t* __restrict__ CL,
                                             int M, int N, int K, int bm, int bn) {
    __shared__ uint32_t As1[64][20], As2[64][20];
    __shared__ uint32_t Bs1[16][68], Bs2[16][68];
    const int tid  = threadIdx.x;
    const int warp = tid >> 5, lane = tid & 31;
    const int qd = lane >> 2, qt = lane & 3;
    const int rbase = (warp >> 1) << 5;
    const int cbase = (warp & 1) << 5;
    const int K2 = K >> 1;

    int arow[2], ac4[2], bk2[2], bn4[2];
#pragma unroll
    for (int i = 0; i < 2; i++) {
        int idx = tid + (i << 7);
        arow[i] = idx >> 2; ac4[i] = (idx & 3) << 2;
        bk2[i] = idx >> 4;  bn4[i] = (idx & 15) << 2;
    }
    uint4 rAH[2], rAL[2], rBH[2], rBL[2];
#pragma unroll
    for (int i = 0; i < 2; i++) {
        int gr = bm + arow[i]; if (gr >= M) gr = M - 1;
        rAH[i] = *(const uint4*)(AH + (size_t)gr * K2 + ac4[i]);
        rAL[i] = *(const uint4*)(AL + (size_t)gr * K2 + ac4[i]);
        rBH[i] = *(const uint4*)(BH + (size_t)bk2[i] * N + bn + bn4[i]);
        rBL[i] = *(const uint4*)(BL + (size_t)bk2[i] * N + bn + bn4[i]);
    }

    float acc[2][4][4] = {};
    const int iters = K >> 5;
    for (int it = 0; it < iters; it++) {
#pragma unroll
        for (int i = 0; i < 2; i++) {
            *(uint4*)&As1[arow[i]][ac4[i]] = rAH[i];
            *(uint4*)&As2[arow[i]][ac4[i]] = rAL[i];
            *(uint4*)&Bs1[bk2[i]][bn4[i]] = rBH[i];
            *(uint4*)&Bs2[bk2[i]][bn4[i]] = rBL[i];
        }
        __syncthreads();
        if (it + 1 < iters) {
            int koff = (it + 1) << 4;
#pragma unroll
            for (int i = 0; i < 2; i++) {
                int gr = bm + arow[i]; if (gr >= M) gr = M - 1;
                rAH[i] = *(const uint4*)(AH + (size_t)gr * K2 + koff + ac4[i]);
                rAL[i] = *(const uint4*)(AL + (size_t)gr * K2 + koff + ac4[i]);
                rBH[i] = *(const uint4*)(BH + (size_t)(koff + bk2[i]) * N + bn + bn4[i]);
                rBL[i] = *(const uint4*)(BL + (size_t)(koff + bk2[i]) * N + bn + bn4[i]);
            }
        }
#pragma unroll
        for (int s = 0; s < 2; s++) {
            uint32_t A1[2][4], A2[2][4];
#pragma unroll
            for (int rg = 0; rg < 2; rg++) {
                int r = rbase + (rg << 4);
                A1[rg][0] = As1[r + qd    ][s * 8 + qt];
                A1[rg][1] = As1[r + qd + 8][s * 8 + qt];
                A1[rg][2] = As1[r + qd    ][s * 8 + qt + 4];
                A1[rg][3] = As1[r + qd + 8][s * 8 + qt + 4];
                A2[rg][0] = As2[r + qd    ][s * 8 + qt];
                A2[rg][1] = As2[r + qd + 8][s * 8 + qt];
                A2[rg][2] = As2[r + qd    ][s * 8 + qt + 4];
                A2[rg][3] = As2[r + qd + 8][s * 8 + qt + 4];
            }
#pragma unroll
            for (int j = 0; j < 4; j++) {
                int col = cbase + j * 8 + qd;
                uint32_t b10 = Bs1[s * 8 + qt    ][col];
                uint32_t b11 = Bs1[s * 8 + qt + 4][col];
                uint32_t b20 = Bs2[s * 8 + qt    ][col];
                uint32_t b21 = Bs2[s * 8 + qt + 4][col];
#pragma unroll
                for (int rg = 0; rg < 2; rg++) {
                    mma_bf16(acc[rg][j], A1[rg][0], A1[rg][1], A1[rg][2], A1[rg][3], b20, b21);
                    mma_bf16(acc[rg][j], A2[rg][0], A2[rg][1], A2[rg][2], A2[rg][3], b10, b11);
                    mma_bf16(acc[rg][j], A1[rg][0], A1[rg][1], A1[rg][2], A1[rg][3], b10, b11);
                }
            }
        }
        __syncthreads();
    }
    const int N2 = N >> 1;
#pragma unroll
    for (int rg = 0; rg < 2; rg++) {
        int ra0 = bm + rbase + (rg << 4) + qd, ra1 = ra0 + 8;
#pragma unroll
        for (int j = 0; j < 4; j++) {
            int col = bn + cbase + j * 8 + (qt << 1);
            float b0 = bias[col], b1 = bias[col + 1];
            float v0 = acc[rg][j][0] + b0, v1 = acc[rg][j][1] + b1;
            float v2 = acc[rg][j][2] + b0, v3 = acc[rg][j][3] + b1;
            if (RELU) {
                v0 = fmaxf(v0, 0.f); v1 = fmaxf(v1, 0.f);
                v2 = fmaxf(v2, 0.f); v3 = fmaxf(v3, 0.f);
            }
            if (PACKOUT) {
                if (ra0 < M) {
                    size_t i0 = (size_t)ra0 * N2 + (col >> 1);
                    split2(v0, v1, CH[i0], CL[i0]);
                }
                if (ra1 < M) {
                    size_t i1 = (size_t)ra1 * N2 + (col >> 1);
                    split2(v2, v3, CH[i1], CL[i1]);
                }
            } else {
                if (ra0 < M) *(float2*)(C + (size_t)ra0 * N + col) = make_float2(v0, v1);
                if (ra1 < M) *(float2*)(C + (size_t)ra1 * N + col) = make_float2(v2, v3);
            }
        }
    }
}

template <bool RELU, bool PACKOUT>
__global__ void __launch_bounds__(128) gemm_pk(const uint32_t* __restrict__ AH,
                                               const uint32_t* __restrict__ AL,
                                               const uint32_t* __restrict__ BH,
                                               const uint32_t* __restrict__ BL,
                                               const float* __restrict__ bias,
                                               float* C, uint32_t* CH, uint32_t* CL,
                                               int M, int N, int K) {
    gemm_pk_body<RELU, PACKOUT>(AH, AL, BH, BL, bias, C, CH, CL, M, N, K,
                                blockIdx.y << 6, blockIdx.x << 6);
}

__global__ void __launch_bounds__(128) gemm_kv_pk(const uint32_t* __restrict__ AH,
                                                  const uint32_t* __restrict__ AL,
                                                  const float* __restrict__ bk,
                                                  const float* __restrict__ bv,
                                                  float* __restrict__ kall,
                                                  float* __restrict__ vall) {
    const int z = blockIdx.z;
    const int l = z >> 1;
    const bool isv = z & 1;
    const uint32_t* BH = (isv ? g_WvH : g_WkH) + (size_t)l * 128 * 256;
    const uint32_t* BL = (isv ? g_WvL : g_WkL) + (size_t)l * 128 * 256;
    const float* bias  = (isv ? bv : bk) + (size_t)l * EE;
    float* C           = (isv ? vall : kall) + (size_t)l * MMEM * EE;
    gemm_pk_body<false, false>(AH, AL, BH, BL, bias, C, nullptr, nullptr,
                               MMEM, EE, EE, blockIdx.y << 6, blockIdx.x << 6);
}

// ---------------- bf16 flash attention (QK + swapped AV), packed attn out ---------
__global__ void __launch_bounds__(128) flash_bf_kernel(const float* __restrict__ Q,
                                                       const float* __restrict__ Km,
                                                       const float* __restrict__ Vm,
                                                       uint32_t* __restrict__ OH,
                                                       uint32_t* __restrict__ OL) {
    const int h  = blockIdx.y;
    const int pb = blockIdx.x << 6;
    __shared__ uint32_t Qs2[64][20];
    __shared__ uint32_t Ks2[16][72];
    __shared__ uint32_t Vs2[32][36];
    __shared__ uint32_t PT2[32][72];
    __shared__ float    lsums[64];
    const int tid  = threadIdx.x;
    const int warp = tid >> 5, lane = tid & 31;
    const int qd = lane >> 2, qt = lane & 3;
    const int r0 = (warp << 4) + qd;

    {
        const float alpha = 0.17677669529663687f;
#pragma unroll
        for (int i = 0; i < 4; i++) {
            int idx = tid + (i << 7);
            int row = idx >> 3, f4 = idx & 7;
            float4 v = *(const float4*)(Q + (size_t)(pb + row) * EE + h * DH + (f4 << 2));
            Qs2[row][f4 * 2]     = pack_bf2(v.x * alpha, v.y * alpha);
            Qs2[row][f4 * 2 + 1] = pack_bf2(v.z * alpha, v.w * alpha);
        }
    }
    float oacc[2][2][4] = {};
    float lsum0 = 0.f, lsum1 = 0.f;
    __syncthreads();

    for (int mb = 0; mb < MMEM; mb += 64) {
#pragma unroll
        for (int i = 0; i < 4; i++) {
            int idx = tid + (i << 7);
            int m = idx >> 3, f4 = idx & 7;
            float4 kv = *(const float4*)(Km + (size_t)(mb + m) * EE + h * DH + (f4 << 2));
            Ks2[f4 * 2][m]     = pack_bf2(kv.x, kv.y);
            Ks2[f4 * 2 + 1][m] = pack_bf2(kv.z, kv.w);
        }
#pragma unroll
        for (int i = 0; i < 2; i++) {
            int idx = tid + (i << 7);
            int m2 = idx >> 3, f4 = idx & 7, d0 = f4 << 2;
            float4 v0 = *(const float4*)(Vm + (size_t)(mb + 2 * m2)     * EE + h * DH + d0);
            float4 v1 = *(const float4*)(Vm + (size_t)(mb + 2 * m2 + 1) * EE + h * DH + d0);
            Vs2[d0 + 0][m2] = pack_bf2(v0.x, v1.x);
            Vs2[d0 + 1][m2] = pack_bf2(v0.y, v1.y);
            Vs2[d0 + 2][m2] = pack_bf2(v0.z, v1.z);
            Vs2[d0 + 3][m2] = pack_bf2(v0.w, v1.w);
        }
        __syncthreads();

        float sacc[8][4] = {};
#pragma unroll
        for (int s = 0; s < 2; s++) {
            uint32_t a0 = Qs2[r0    ][s * 8 + qt];
            uint32_t a1 = Qs2[r0 + 8][s * 8 + qt];
            uint32_t a2 = Qs2[r0    ][s * 8 + qt + 4];
            uint32_t a3 = Qs2[r0 + 8][s * 8 + qt + 4];
#pragma unroll
            for (int j = 0; j < 8; j++) {
                uint32_t b0 = Ks2[s * 8 + qt    ][j * 8 + qd];
                uint32_t b1 = Ks2[s * 8 + qt + 4][j * 8 + qd];
                mma_bf16(sacc[j], a0, a1, a2, a3, b0, b1);
            }
        }

#pragma unroll
        for (int j = 0; j < 8; j++) {
            float e0 = __expf(sacc[j][0]), e1 = __expf(sacc[j][1]);
            float e2 = __expf(sacc[j][2]), e3 = __expf(sacc[j][3]);
            lsum0 += e0 + e1; lsum1 += e2 + e3;
            PT2[j * 4 + qt][r0]     = pack_bf2(e0, e1);
            PT2[j * 4 + qt][r0 + 8] = pack_bf2(e2, e3);
        }
        __syncwarp();

#pragma unroll
        for (int s = 0; s < 4; s++) {
            uint32_t va[2][4];
#pragma unroll
            for (int rg = 0; rg < 2; rg++) {
                int dr = (rg << 4) + qd;
                va[rg][0] = Vs2[dr    ][s * 8 + qt];
                va[rg][1] = Vs2[dr + 8][s * 8 + qt];
                va[rg][2] = Vs2[dr    ][s * 8 + qt + 4];
                va[rg][3] = Vs2[dr + 8][s * 8 + qt + 4];
            }
#pragma unroll
            for (int j = 0; j < 2; j++) {
                int pcol = (warp << 4) + j * 8 + qd;
                uint32_t b0 = PT2[s * 8 + qt    ][pcol];
                uint32_t b1 = PT2[s * 8 + qt + 4][pcol];
#pragma unroll
                for (int rg = 0; rg < 2; rg++)
                    mma_bf16(oacc[rg][j], va[rg][0], va[rg][1], va[rg][2], va[rg][3], b0, b1);
            }
        }
        __syncthreads();
    }

    lsum0 += __shfl_xor_sync(0xffffffffu, lsum0, 1);
    lsum0 += __shfl_xor_sync(0xffffffffu, lsum0, 2);
    lsum1 += __shfl_xor_sync(0xffffffffu, lsum1, 1);
    lsum1 += __shfl_xor_sync(0xffffffffu, lsum1, 2);
    if (qt == 0) { lsums[r0] = lsum0; lsums[r0 + 8] = lsum1; }
    __syncwarp();

    // packed output: pairs along d (qd even pairs with qd+1 = lane+4)
#pragma unroll
    for (int j = 0; j < 2; j++) {
        int p0 = (warp << 4) + j * 8 + (qt << 1);
        float inv0 = 1.0f / lsums[p0];
        float inv1 = 1.0f / lsums[p0 + 1];
#pragma unroll
        for (int rg = 0; rg < 2; rg++) {
            int d = (rg << 4) + qd;
            float v00 = oacc[rg][j][0] * inv0;  // (p0,   d)
            float v10 = oacc[rg][j][1] * inv1;  // (p0+1, d)
            float v08 = oacc[rg][j][2] * inv0;  // (p0,   d+8)
            float v18 = oacc[rg][j][3] * inv1;  // (p0+1, d+8)
            float p00 = __shfl_down_sync(0xffffffffu, v00, 4);
            float p10 = __shfl_down_sync(0xffffffffu, v10, 4);
            float p08 = __shfl_down_sync(0xffffffffu, v08, 4);
            float p18 = __shfl_down_sync(0xffffffffu, v18, 4);
            if ((qd & 1) == 0) {
                int c0 = (h * DH + d) >> 1;
                int c8 = (h * DH + d + 8) >> 1;
                size_t i00 = (size_t)(pb + p0) * 128 + c0;
                size_t i10 = (size_t)(pb + p0 + 1) * 128 + c0;
                size_t i08 = (size_t)(pb + p0) * 128 + c8;
                size_t i18 = (size_t)(pb + p0 + 1) * 128 + c8;
                split2(v00, p00, OH[i00], OL[i00]);
                split2(v10, p10, OH[i10], OL[i10]);
                split2(v08, p08, OH[i08], OL[i08]);
                split2(v18, p18, OH[i18], OL[i18]);
            }
        }
    }
}

// q = LayerNorm(q + resid) * g + b ; also emits packed q
__global__ void add_ln_kernel(float* __restrict__ Qb, const float* __restrict__ R,
                              const float* __restrict__ g, const float* __restrict__ b,
                              uint32_t* __restrict__ QH, uint32_t* __restrict__ QL) {
    const int p = blockIdx.x;
    const int e = threadIdx.x;
    __shared__ float sh[8];
    float x = Qb[(size_t)p * EE + e] + R[(size_t)p * EE + e];
    float s = x;
#pragma unroll
    for (int o = 16; o > 0; o >>= 1) s += __shfl_xor_sync(0xffffffffu, s, o);
    if ((e & 31) == 0) sh[e >> 5] = s;
    __syncthreads();
    float mean = (sh[0] + sh[1] + sh[2] + sh[3] + sh[4] + sh[5] + sh[6] + sh[7]) * (1.0f / 256.0f);
    float d = x - mean;
    __syncthreads();
    s = d * d;
#pragma unroll
    for (int o = 16; o > 0; o >>= 1) s += __shfl_xor_sync(0xffffffffu, s, o);
    if ((e & 31) == 0) sh[e >> 5] = s;
    __syncthreads();
    float var = (sh[0] + sh[1] + sh[2] + sh[3] + sh[4] + sh[5] + sh[6] + sh[7]) * (1.0f / 256.0f);
    float val = d * rsqrtf(var + 1e-5f) * g[e] + b[e];
    Qb[(size_t)p * EE + e] = val;
    float part = __shfl_down_sync(0xffffffffu, val, 1);
    if ((e & 1) == 0) {
        size_t i = (size_t)p * 128 + (e >> 1);
        split2(val, part, QH[i], QL[i]);
    }
}

__global__ void idx_kernel(const float* __restrict__ refs, int* __restrict__ rows,
                           int* __restrict__ cols, float* __restrict__ rfx,
                           float* __restrict__ rfy) {
    int p = blockIdx.x * blockDim.x + threadIdx.x;
    if (p >= PAIRS) return;
    int r = 0, off = 0;
    while (p >= off + (NQ - 1 - r)) { off += NQ - 1 - r; r++; }
    int c = r + 1 + (p - off);
    rows[p] = r; cols[p] = c;
    rfx[p] = 0.5f * (refs[r * 4 + 0] + refs[c * 4 + 0]);
    rfy[p] = 0.5f * (refs[r * 4 + 1] + refs[c * 4 + 1]);
}

// pair concat, packed directly (K=512 -> 256 k2 per row)
__global__ void pairc_kernel(const float* __restrict__ H, const int* __restrict__ rows,
                             const int* __restrict__ cols,
                             uint32_t* __restrict__ PCH, uint32_t* __restrict__ PCL) {
    const int p = blockIdx.x;
    const int e = threadIdx.x;   // k2 index 0..255
    int r = rows[p], c = cols[p];
    const float* src = (e < 128) ? (H + (size_t)r * EE + 2 * e)
                                 : (H + (size_t)c * EE + 2 * (e - 128));
    float2 v = *(const float2*)src;
    size_t i = (size_t)p * 256 + e;
    split2(v.x, v.y, PCH[i], PCL[i]);
}

__global__ void addref_kernel(float* __restrict__ Qb, const float* __restrict__ rfx,
                              const float* __restrict__ rfy, const float* __restrict__ Wref,
                              uint32_t* __restrict__ QH, uint32_t* __restrict__ QL) {
    const int p = blockIdx.x;
    const int e = threadIdx.x;
    float val = Qb[(size_t)p * EE + e] + rfx[p] * Wref[e] + rfy[p] * Wref[EE + e];
    Qb[(size_t)p * EE + e] = val;
    float part = __shfl_down_sync(0xffffffffu, val, 1);
    if ((e & 1) == 0) {
        size_t i = (size_t)p * 128 + (e >> 1);
        split2(val, part, QH[i], QL[i]);
    }
}

__global__ void score_kernel(const float* __restrict__ Qb, const float* __restrict__ Tx,
                             const float* __restrict__ lsc, const int* __restrict__ rows,
                             const int* __restrict__ cols, float* __restrict__ out) {
    const int pp = blockIdx.x;
    __shared__ float qr[EE];
    const int tid = threadIdx.x;
    qr[tid] = Qb[(size_t)pp * EE + tid];
    __syncthreads();
    const float scale = expf(lsc[0]);
    const int w = tid >> 5, lane = tid & 31;
    const int r = rows[pp], c = cols[pp];
    for (int t = w; t < TTXT; t += 8) {
        float sum = 0.0f;
#pragma unroll
        for (int i = 0; i < 8; i++)
            sum = fmaf(qr[lane + (i << 5)], Tx[(size_t)t * EE + lane + (i << 5)], sum);
#pragma unroll
        for (int o = 16; o > 0; o >>= 1) sum += __shfl_down_sync(0xffffffffu, sum, o);
        if (lane == 0) {
            float vv = sum * scale;
            out[(size_t)(r * NQ + c) * TTXT + t] = vv;
            out[(size_t)(c * NQ + r) * TTXT + t] = vv;
        }
    }
}

// ----------------------------------- launcher ------------------------------------
extern "C" void kernel_launch(void* const* d_in, const int* in_sizes, int n_in,
                              void* d_out, int out_size) {
    const float* hid    = (const float*)d_in[0];
    const float* memin  = (const float*)d_in[1];
    const float* refs   = (const float*)d_in[2];
    const float* mtext  = (const float*)d_in[3];
    const float* W_pair = (const float*)d_in[6];
    const float* b_pair = (const float*)d_in[7];
    const float* W_mem  = (const float*)d_in[8];
    const float* b_mem  = (const float*)d_in[9];
    const float* W_text = (const float*)d_in[10];
    const float* b_text = (const float*)d_in[11];
    const float* W_ref  = (const float*)d_in[12];
    const float* Wq = (const float*)d_in[13]; const float* bq = (const float*)d_in[14];
    const float* Wk = (const float*)d_in[15]; const float* bk = (const float*)d_in[16];
    const float* Wv = (const float*)d_in[17]; const float* bv = (const float*)d_in[18];
    const float* Wo = (const float*)d_in[19]; const float* bo = (const float*)d_in[20];
    const float* ln1g = (const float*)d_in[21]; const float* ln1b = (const float*)d_in[22];
    const float* ln2g = (const float*)d_in[23]; const float* ln2b = (const float*)d_in[24];
    const float* Wf1 = (const float*)d_in[25]; const float* bf1 = (const float*)d_in[26];
    const float* Wf2 = (const float*)d_in[27]; const float* bf2 = (const float*)d_in[28];
    const float* lsc = (const float*)d_in[29];
    float* out = (float*)d_out;

    float *q, *qh, *kall, *vall, *proj, *text, *rfx, *rfy;
    int *rowp, *colp;
    uint32_t *WpairH, *WpairL, *WmemH, *WmemL, *WtextH, *WtextL;
    uint32_t *WqH, *WqL, *WoH, *WoL, *Wf1H, *Wf1L, *Wf2H, *Wf2L;
    uint32_t *WkH, *WkL, *WvH, *WvL;
    uint32_t *pcH, *pcL, *qPH, *qPL, *minH, *minL, *mtxH, *mtxL;
    uint32_t *memH, *memL, *atH, *atL, *ffH, *ffL;
    cudaGetSymbolAddress((void**)&q,    g_q);
    cudaGetSymbolAddress((void**)&qh,   g_qh);
    cudaGetSymbolAddress((void**)&kall, g_kall);
    cudaGetSymbolAddress((void**)&vall, g_vall);
    cudaGetSymbolAddress((void**)&proj, g_proj);
    cudaGetSymbolAddress((void**)&text, g_text);
    cudaGetSymbolAddress((void**)&rowp, g_rowi);
    cudaGetSymbolAddress((void**)&colp, g_coli);
    cudaGetSymbolAddress((void**)&rfx,  g_refx);
    cudaGetSymbolAddress((void**)&rfy,  g_refy);
    cudaGetSymbolAddress((void**)&WpairH, g_WpairH); cudaGetSymbolAddress((void**)&WpairL, g_WpairL);
    cudaGetSymbolAddress((void**)&WmemH,  g_WmemH);  cudaGetSymbolAddress((void**)&WmemL,  g_WmemL);
    cudaGetSymbolAddress((void**)&WtextH, g_WtextH); cudaGetSymbolAddress((void**)&WtextL, g_WtextL);
    cudaGetSymbolAddress((void**)&WqH, g_WqH); cudaGetSymbolAddress((void**)&WqL, g_WqL);
    cudaGetSymbolAddress((void**)&WkH, g_WkH); cudaGetSymbolAddress((void**)&WkL, g_WkL);
    cudaGetSymbolAddress((void**)&WvH, g_WvH); cudaGetSymbolAddress((void**)&WvL, g_WvL);
    cudaGetSymbolAddress((void**)&WoH, g_WoH); cudaGetSymbolAddress((void**)&WoL, g_WoL);
    cudaGetSymbolAddress((void**)&Wf1H, g_Wf1H); cudaGetSymbolAddress((void**)&Wf1L, g_Wf1L);
    cudaGetSymbolAddress((void**)&Wf2H, g_Wf2H); cudaGetSymbolAddress((void**)&Wf2L, g_Wf2L);
    cudaGetSymbolAddress((void**)&pcH, g_pcH);   cudaGetSymbolAddress((void**)&pcL, g_pcL);
    cudaGetSymbolAddress((void**)&qPH, g_qPH);   cudaGetSymbolAddress((void**)&qPL, g_qPL);
    cudaGetSymbolAddress((void**)&minH, g_minH); cudaGetSymbolAddress((void**)&minL, g_minL);
    cudaGetSymbolAddress((void**)&mtxH, g_mtxH); cudaGetSymbolAddress((void**)&mtxL, g_mtxL);
    cudaGetSymbolAddress((void**)&memH, g_memH); cudaGetSymbolAddress((void**)&memL, g_memL);
    cudaGetSymbolAddress((void**)&atH, g_atH);   cudaGetSymbolAddress((void**)&atL, g_atL);
    cudaGetSymbolAddress((void**)&ffH, g_ffH);   cudaGetSymbolAddress((void**)&ffL, g_ffL);

    // ---- pack weights + static activations ----
    pack_w<<<(65536 + 255) / 256, 256>>>(W_pair, WpairH, WpairL, 512, 256, 65536);
    pack_w<<<(32768 + 255) / 256, 256>>>(W_mem,  WmemH,  WmemL,  256, 256, 32768);
    pack_w<<<(32768 + 255) / 256, 256>>>(W_text, WtextH, WtextL, 256, 256, 32768);
    pack_w<<<(131072 + 255) / 256, 256>>>(Wq, WqH, WqL, 256, 256, 131072);
    pack_w<<<(131072 + 255) / 256, 256>>>(Wk, WkH, WkL, 256, 256, 131072);
    pack_w<<<(131072 + 255) / 256, 256>>>(Wv, WvH, WvL, 256, 256, 131072);
    pack_w<<<(131072 + 255) / 256, 256>>>(Wo, WoH, WoL, 256, 256, 131072);
    pack_w<<<(524288 + 255) / 256, 256>>>(Wf1, Wf1H, Wf1L, 256, 1024, 524288);
    pack_w<<<(524288 + 255) / 256, 256>>>(Wf2, Wf2H, Wf2L, 1024, 256, 524288);
    pack_a<<<(524288 + 255) / 256, 256>>>(memin, minH, minL, 524288);
    pack_a<<<(4096 + 255) / 256, 256>>>(mtext, mtxH, mtxL, 4096);

    idx_kernel<<<8, 256>>>(refs, rowp, colp, rfx, rfy);
    pairc_kernel<<<PAIRS, 256>>>(hid, rowp, colp, pcH, pcL);
    gemm_pk<false, false><<<dim3(4, 32), 128>>>(pcH, pcL, WpairH, WpairL, b_pair,
                                                q, nullptr, nullptr, PAIRS, EE, 512);
    addref_kernel<<<PAIRS, 256>>>(q, rfx, rfy, W_ref, qPH, qPL);
    gemm_pk<false, true><<<dim3(4, 64), 128>>>(minH, minL, WmemH, WmemL, b_mem,
                                               nullptr, memH, memL, MMEM, EE, EE);
    gemm_pk<false, false><<<dim3(4, 1), 128>>>(mtxH, mtxL, WtextH, WtextL, b_text,
                                               text, nullptr, nullptr, TTXT, EE, EE);
    gemm_kv_pk<<<dim3(4, 64, 2 * LLAYERS), 128>>>(memH, memL, bk, bv, kall, vall);

    for (int l = 0; l < LLAYERS; l++) {
        gemm_pk<false, false><<<dim3(4, 32), 128>>>(qPH, qPL, WqH + (size_t)l * 32768,
                                                    WqL + (size_t)l * 32768, bq + l * EE,
                                                    qh, nullptr, nullptr, PAIRS, EE, EE);
        flash_bf_kernel<<<dim3(PPAD / 64, HN), 128>>>(qh, kall + (size_t)l * MMEM * EE,
                                                      vall + (size_t)l * MMEM * EE, atH, atL);
        gemm_pk<false, false><<<dim3(4, 32), 128>>>(atH, atL, WoH + (size_t)l * 32768,
                                                    WoL + (size_t)l * 32768, bo + l * EE,
                                                    proj, nullptr, nullptr, PAIRS, EE, EE);
        add_ln_kernel<<<PAIRS, 256>>>(q, proj, ln1g + l * EE, ln1b + l * EE, qPH, qPL);
        gemm_pk<true, true><<<dim3(16, 32), 128>>>(qPH, qPL, Wf1H + (size_t)l * 131072,
                                                   Wf1L + (size_t)l * 131072, bf1 + l * FFD,
                                                   nullptr, ffH, ffL, PAIRS, FFD, EE);
        gemm_pk<false, false><<<dim3(4, 32), 128>>>(ffH, ffL, Wf2H + (size_t)l * 131072,
                                                    Wf2L + (size_t)l * 131072, bf2 + l * EE,
                                                    proj, nullptr, nullptr, PAIRS, EE, FFD);
        add_ln_kernel<<<PAIRS, 256>>>(q, proj, ln2g + l * EE, ln2b + l * EE, qPH, qPL);
    }

    cudaMemsetAsync(d_out, 0, (size_t)out_size * sizeof(float), 0);
    score_kernel<<<PAIRS, 256>>>(q, text, lsc, rowp, colp, out);
}

// round 10
// speedup vs baseline: 1.0122x; 1.0122x over previous
#include <cuda_runtime.h>
#include <cstdint>

#define EE 256
#define HN 8
#define DH 32
#define LLAYERS 4
#define FFD 1024
#define NQ 64
#define PAIRS 2016
#define PPAD 2048
#define MMEM 4096
#define TTXT 32

// ---------------- scratch (static device globals; allocation-free) ----------------
__device__ float g_q[PPAD * EE];
__device__ float g_qh[PPAD * EE];
__device__ float g_kall[LLAYERS * MMEM * EE];
__device__ float g_vall[LLAYERS * MMEM * EE];
__device__ float g_proj[PPAD * EE];
__device__ float g_text[TTXT * EE];
__device__ int   g_rowi[PAIRS];
__device__ int   g_coli[PAIRS];
__device__ float g_refx[PAIRS];
__device__ float g_refy[PAIRS];

// packed weights (hi/lo bf16x2 over k-pairs): WH[k2][n]
__device__ uint32_t g_WpairH[256 * 256], g_WpairL[256 * 256];
__device__ uint32_t g_WmemH[128 * 256],  g_WmemL[128 * 256];
__device__ uint32_t g_WtextH[128 * 256], g_WtextL[128 * 256];
__device__ uint32_t g_WqH[LLAYERS * 128 * 256], g_WqL[LLAYERS * 128 * 256];
__device__ uint32_t g_WkH[LLAYERS * 128 * 256], g_WkL[LLAYERS * 128 * 256];
__device__ uint32_t g_WvH[LLAYERS * 128 * 256], g_WvL[LLAYERS * 128 * 256];
__device__ uint32_t g_WoH[LLAYERS * 128 * 256], g_WoL[LLAYERS * 128 * 256];
__device__ uint32_t g_Wf1H[LLAYERS * 128 * 1024], g_Wf1L[LLAYERS * 128 * 1024];
__device__ uint32_t g_Wf2H[LLAYERS * 512 * 256],  g_Wf2L[LLAYERS * 512 * 256];
// packed activations: AH[m][k2]
__device__ uint32_t g_pcH[PPAD * 256],  g_pcL[PPAD * 256];
__device__ uint32_t g_qPH[PPAD * 128],  g_qPL[PPAD * 128];
__device__ uint32_t g_minH[MMEM * 128], g_minL[MMEM * 128];
__device__ uint32_t g_mtxH[TTXT * 128], g_mtxL[TTXT * 128];
__device__ uint32_t g_memH[MMEM * 128], g_memL[MMEM * 128];
__device__ uint32_t g_atH[PPAD * 128],  g_atL[PPAD * 128];
__device__ uint32_t g_ffH[PPAD * 512],  g_ffL[PPAD * 512];

__device__ __forceinline__ void mma_bf16(float* c, uint32_t a0, uint32_t a1,
                                         uint32_t a2, uint32_t a3,
                                         uint32_t b0, uint32_t b1) {
    asm volatile(
        "mma.sync.aligned.m16n8k16.row.col.f32.bf16.bf16.f32 "
        "{%0,%1,%2,%3}, {%4,%5,%6,%7}, {%8,%9}, {%0,%1,%2,%3};\n"
        : "+f"(c[0]), "+f"(c[1]), "+f"(c[2]), "+f"(c[3])
        : "r"(a0), "r"(a1), "r"(a2), "r"(a3), "r"(b0), "r"(b1));
}

__device__ __forceinline__ uint32_t pack_bf2(float e_lo, float e_hi) {
    uint32_t r;
    asm("cvt.rn.bf16x2.f32 %0, %1, %2;" : "=r"(r) : "f"(e_hi), "f"(e_lo));
    return r;
}
__device__ __forceinline__ float bf_lo(uint32_t p) { return __uint_as_float(p << 16); }
__device__ __forceinline__ float bf_hi(uint32_t p) { return __uint_as_float(p & 0xffff0000u); }
__device__ __forceinline__ void split2(float a, float b, uint32_t& h, uint32_t& l) {
    h = pack_bf2(a, b);
    l = pack_bf2(a - bf_lo(h), b - bf_hi(h));
}

// ---------------- ONE fused pack kernel --------------------------------------------
__device__ __forceinline__ void pw_seg(const float* __restrict__ s,
                                       uint32_t* __restrict__ H, uint32_t* __restrict__ L,
                                       int g, int K, int N) {
    int half = (K >> 1) * N;
    int l = g / half, r = g - l * half;
    int k2 = r / N, n = r - k2 * N;
    const float* p = s + (size_t)l * K * N;
    split2(p[(size_t)(2 * k2) * N + n], p[(size_t)(2 * k2 + 1) * N + n], H[g], L[g]);
}
__device__ __forceinline__ void pa_seg(const float* __restrict__ s,
                                       uint32_t* __restrict__ H, uint32_t* __restrict__ L,
                                       int g) {
    float2 v = *(const float2*)(s + 2 * (size_t)g);
    split2(v.x, v.y, H[g], L[g]);
}

#define S_WPAIR 65536
#define S_WMEM  32768
#define S_WTEXT 32768
#define S_W4    131072
#define S_WFF   524288
#define S_MIN   524288
#define S_MTX   4096
#define PACK_TOTAL (S_WPAIR + S_WMEM + S_WTEXT + 4 * S_W4 + 2 * S_WFF + S_MIN + S_MTX)

__global__ void __launch_bounds__(256) pack_all(
    const float* __restrict__ W_pair, const float* __restrict__ W_mem,
    const float* __restrict__ W_text, const float* __restrict__ Wq,
    const float* __restrict__ Wk, const float* __restrict__ Wv,
    const float* __restrict__ Wo, const float* __restrict__ Wf1,
    const float* __restrict__ Wf2, const float* __restrict__ memin,
    const float* __restrict__ mtext) {
    int g = blockIdx.x * 256 + threadIdx.x;
    if (g < S_WPAIR) { pw_seg(W_pair, g_WpairH, g_WpairL, g, 512, 256); return; }
    g -= S_WPAIR;
    if (g < S_WMEM)  { pw_seg(W_mem,  g_WmemH,  g_WmemL,  g, 256, 256); return; }
    g -= S_WMEM;
    if (g < S_WTEXT) { pw_seg(W_text, g_WtextH, g_WtextL, g, 256, 256); return; }
    g -= S_WTEXT;
    if (g < S_W4) { pw_seg(Wq, g_WqH, g_WqL, g, 256, 256); return; }
    g -= S_W4;
    if (g < S_W4) { pw_seg(Wk, g_WkH, g_WkL, g, 256, 256); return; }
    g -= S_W4;
    if (g < S_W4) { pw_seg(Wv, g_WvH, g_WvL, g, 256, 256); return; }
    g -= S_W4;
    if (g < S_W4) { pw_seg(Wo, g_WoH, g_WoL, g, 256, 256); return; }
    g -= S_W4;
    if (g < S_WFF) { pw_seg(Wf1, g_Wf1H, g_Wf1L, g, 256, 1024); return; }
    g -= S_WFF;
    if (g < S_WFF) { pw_seg(Wf2, g_Wf2H, g_Wf2L, g, 1024, 256); return; }
    g -= S_WFF;
    if (g < S_MIN) { pa_seg(memin, g_minH, g_minL, g); return; }
    g -= S_MIN;
    if (g < S_MTX) { pa_seg(mtext, g_mtxH, g_mtxL, g); }
}

// ---------------- double-buffered packed bf16x2 3-product GEMM --------------------
// block 64x64, BK=32, 128 thr (4 warps), warp tile 32x32; 1 barrier per iter.
template <bool RELU, bool PACKOUT>
__device__ __forceinline__ void gemm_pk_body(const uint32_t* __restrict__ AH,
                                             const uint32_t* __restrict__ AL,
                                             const uint32_t* __restrict__ BH,
                                             const uint32_t* __restrict__ BL,
                                             const float* __restrict__ bias,
                                             float* __restrict__ C,
                                             uint32_t* __restrict__ CH,
                                             uint32_t* __restrict__ CL,
                                             int M, int N, int K, int bm, int bn) {
    __shared__ uint32_t As1[2][64][20], As2[2][64][20];
    __shared__ uint32_t Bs1[2][16][68], Bs2[2][16][68];
    const int tid  = threadIdx.x;
    const int warp = tid >> 5, lane = tid & 31;
    const int qd = lane >> 2, qt = lane & 3;
    const int rbase = (warp >> 1) << 5;
    const int cbase = (warp & 1) << 5;
    const int K2 = K >> 1;

    int arow[2], ac4[2], bk2[2], bn4[2];
#pragma unroll
    for (int i = 0; i < 2; i++) {
        int idx = tid + (i << 7);
        arow[i] = idx >> 2; ac4[i] = (idx & 3) << 2;
        bk2[i] = idx >> 4;  bn4[i] = (idx & 15) << 2;
    }
    int agr[2];
#pragma unroll
    for (int i = 0; i < 2; i++) {
        int gr = bm + arow[i]; if (gr >= M) gr = M - 1;
        agr[i] = gr;
    }
    uint4 rAH[2], rAL[2], rBH[2], rBL[2];
#pragma unroll
    for (int i = 0; i < 2; i++) {
        rAH[i] = *(const uint4*)(AH + (size_t)agr[i] * K2 + ac4[i]);
        rAL[i] = *(const uint4*)(AL + (size_t)agr[i] * K2 + ac4[i]);
        rBH[i] = *(const uint4*)(BH + (size_t)bk2[i] * N + bn + bn4[i]);
        rBL[i] = *(const uint4*)(BL + (size_t)bk2[i] * N + bn + bn4[i]);
    }
    // prologue: fill stage 0
#pragma unroll
    for (int i = 0; i < 2; i++) {
        *(uint4*)&As1[0][arow[i]][ac4[i]] = rAH[i];
        *(uint4*)&As2[0][arow[i]][ac4[i]] = rAL[i];
        *(uint4*)&Bs1[0][bk2[i]][bn4[i]] = rBH[i];
        *(uint4*)&Bs2[0][bk2[i]][bn4[i]] = rBL[i];
    }
    __syncthreads();

    float acc[2][4][4] = {};
    const int iters = K >> 5;
    for (int it = 0; it < iters; it++) {
        const int cur = it & 1;
        if (it + 1 < iters) {
            int koff = (it + 1) << 4;
#pragma unroll
            for (int i = 0; i < 2; i++) {
                rAH[i] = *(const uint4*)(AH + (size_t)agr[i] * K2 + koff + ac4[i]);
                rAL[i] = *(const uint4*)(AL + (size_t)agr[i] * K2 + koff + ac4[i]);
                rBH[i] = *(const uint4*)(BH + (size_t)(koff + bk2[i]) * N + bn + bn4[i]);
                rBL[i] = *(const uint4*)(BL + (size_t)(koff + bk2[i]) * N + bn + bn4[i]);
            }
        }
#pragma unroll
        for (int s = 0; s < 2; s++) {
            uint32_t A1[2][4], A2[2][4];
#pragma unroll
            for (int rg = 0; rg < 2; rg++) {
                int r = rbase + (rg << 4);
                A1[rg][0] = As1[cur][r + qd    ][s * 8 + qt];
                A1[rg][1] = As1[cur][r + qd + 8][s * 8 + qt];
                A1[rg][2] = As1[cur][r + qd    ][s * 8 + qt + 4];
                A1[rg][3] = As1[cur][r + qd + 8][s * 8 + qt + 4];
                A2[rg][0] = As2[cur][r + qd    ][s * 8 + qt];
                A2[rg][1] = As2[cur][r + qd + 8][s * 8 + qt];
                A2[rg][2] = As2[cur][r + qd    ][s * 8 + qt + 4];
                A2[rg][3] = As2[cur][r + qd + 8][s * 8 + qt + 4];
            }
#pragma unroll
            for (int j = 0; j < 4; j++) {
                int col = cbase + j * 8 + qd;
                uint32_t b10 = Bs1[cur][s * 8 + qt    ][col];
                uint32_t b11 = Bs1[cur][s * 8 + qt + 4][col];
                uint32_t b20 = Bs2[cur][s * 8 + qt    ][col];
                uint32_t b21 = Bs2[cur][s * 8 + qt + 4][col];
#pragma unroll
                for (int rg = 0; rg < 2; rg++) {
                    mma_bf16(acc[rg][j], A1[rg][0], A1[rg][1], A1[rg][2], A1[rg][3], b20, b21);
                    mma_bf16(acc[rg][j], A2[rg][0], A2[rg][1], A2[rg][2], A2[rg][3], b10, b11);
                    mma_bf16(acc[rg][j], A1[rg][0], A1[rg][1], A1[rg][2], A1[rg][3], b10, b11);
                }
            }
        }
        if (it + 1 < iters) {
            const int nxt = cur ^ 1;
#pragma unroll
            for (int i = 0; i < 2; i++) {
                *(uint4*)&As1[nxt][arow[i]][ac4[i]] = rAH[i];
                *(uint4*)&As2[nxt][arow[i]][ac4[i]] = rAL[i];
                *(uint4*)&Bs1[nxt][bk2[i]][bn4[i]] = rBH[i];
                *(uint4*)&Bs2[nxt][bk2[i]][bn4[i]] = rBL[i];
            }
            __syncthreads();
        }
    }
    const int N2 = N >> 1;
#pragma unroll
    for (int rg = 0; rg < 2; rg++) {
        int ra0 = bm + rbase + (rg << 4) + qd, ra1 = ra0 + 8;
#pragma unroll
        for (int j = 0; j < 4; j++) {
            int col = bn + cbase + j * 8 + (qt << 1);
            float b0 = bias[col], b1 = bias[col + 1];
            float v0 = acc[rg][j][0] + b0, v1 = acc[rg][j][1] + b1;
            float v2 = acc[rg][j][2] + b0, v3 = acc[rg][j][3] + b1;
            if (RELU) {
                v0 = fmaxf(v0, 0.f); v1 = fmaxf(v1, 0.f);
                v2 = fmaxf(v2, 0.f); v3 = fmaxf(v3, 0.f);
            }
            if (PACKOUT) {
                if (ra0 < M) {
                    size_t i0 = (size_t)ra0 * N2 + (col >> 1);
                    split2(v0, v1, CH[i0], CL[i0]);
                }
                if (ra1 < M) {
                    size_t i1 = (size_t)ra1 * N2 + (col >> 1);
                    split2(v2, v3, CH[i1], CL[i1]);
                }
            } else {
                if (ra0 < M) *(float2*)(C + (size_t)ra0 * N + col) = make_float2(v0, v1);
                if (ra1 < M) *(float2*)(C + (size_t)ra1 * N + col) = make_float2(v2, v3);
            }
        }
    }
}

template <bool RELU, bool PACKOUT>
__global__ void __launch_bounds__(128) gemm_pk(const uint32_t* __restrict__ AH,
                                               const uint32_t* __restrict__ AL,
                                               const uint32_t* __restrict__ BH,
                                               const uint32_t* __restrict__ BL,
                                               const float* __restrict__ bias,
                                               float* C, uint32_t* CH, uint32_t* CL,
                                               int M, int N, int K) {
    gemm_pk_body<RELU, PACKOUT>(AH, AL, BH, BL, bias, C, CH, CL, M, N, K,
                                blockIdx.y << 6, blockIdx.x << 6);
}

__global__ void __launch_bounds__(128) gemm_kv_pk(const uint32_t* __restrict__ AH,
                                                  const uint32_t* __restrict__ AL,
                                                  const float* __restrict__ bk,
                                                  const float* __restrict__ bv,
                                                  float* __restrict__ kall,
                                                  float* __restrict__ vall) {
    const int z = blockIdx.z;
    const int l = z >> 1;
    const bool isv = z & 1;
    const uint32_t* BH = (isv ? g_WvH : g_WkH) + (size_t)l * 128 * 256;
    const uint32_t* BL = (isv ? g_WvL : g_WkL) + (size_t)l * 128 * 256;
    const float* bias  = (isv ? bv : bk) + (size_t)l * EE;
    float* C           = (isv ? vall : kall) + (size_t)l * MMEM * EE;
    gemm_pk_body<false, false>(AH, AL, BH, BL, bias, C, nullptr, nullptr,
                               MMEM, EE, EE, blockIdx.y << 6, blockIdx.x << 6);
}

// ---------------- bf16 flash attention (QK + swapped AV), packed attn out ---------
__global__ void __launch_bounds__(128) flash_bf_kernel(const float* __restrict__ Q,
                                                       const float* __restrict__ Km,
                                                       const float* __restrict__ Vm,
                                                       uint32_t* __restrict__ OH,
                                                       uint32_t* __restrict__ OL) {
    const int h  = blockIdx.y;
    const int pb = blockIdx.x << 6;
    __shared__ uint32_t Qs2[64][20];
    __shared__ uint32_t Ks2[16][72];
    __shared__ uint32_t Vs2[32][36];
    __shared__ uint32_t PT2[32][72];
    __shared__ float    lsums[64];
    const int tid  = threadIdx.x;
    const int warp = tid >> 5, lane = tid & 31;
    const int qd = lane >> 2, qt = lane & 3;
    const int r0 = (warp << 4) + qd;

    {
        const float alpha = 0.17677669529663687f;
#pragma unroll
        for (int i = 0; i < 4; i++) {
            int idx = tid + (i << 7);
            int row = idx >> 3, f4 = idx & 7;
            float4 v = *(const float4*)(Q + (size_t)(pb + row) * EE + h * DH + (f4 << 2));
            Qs2[row][f4 * 2]     = pack_bf2(v.x * alpha, v.y * alpha);
            Qs2[row][f4 * 2 + 1] = pack_bf2(v.z * alpha, v.w * alpha);
        }
    }
    float oacc[2][2][4] = {};
    float lsum0 = 0.f, lsum1 = 0.f;
    __syncthreads();

    for (int mb = 0; mb < MMEM; mb += 64) {
#pragma unroll
        for (int i = 0; i < 4; i++) {
            int idx = tid + (i << 7);
            int m = idx >> 3, f4 = idx & 7;
            float4 kv = *(const float4*)(Km + (size_t)(mb + m) * EE + h * DH + (f4 << 2));
            Ks2[f4 * 2][m]     = pack_bf2(kv.x, kv.y);
            Ks2[f4 * 2 + 1][m] = pack_bf2(kv.z, kv.w);
        }
#pragma unroll
        for (int i = 0; i < 2; i++) {
            int idx = tid + (i << 7);
            int m2 = idx >> 3, f4 = idx & 7, d0 = f4 << 2;
            float4 v0 = *(const float4*)(Vm + (size_t)(mb + 2 * m2)     * EE + h * DH + d0);
            float4 v1 = *(const float4*)(Vm + (size_t)(mb + 2 * m2 + 1) * EE + h * DH + d0);
            Vs2[d0 + 0][m2] = pack_bf2(v0.x, v1.x);
            Vs2[d0 + 1][m2] = pack_bf2(v0.y, v1.y);
            Vs2[d0 + 2][m2] = pack_bf2(v0.z, v1.z);
            Vs2[d0 + 3][m2] = pack_bf2(v0.w, v1.w);
        }
        __syncthreads();

        float sacc[8][4] = {};
#pragma unroll
        for (int s = 0; s < 2; s++) {
            uint32_t a0 = Qs2[r0    ][s * 8 + qt];
            uint32_t a1 = Qs2[r0 + 8][s * 8 + qt];
            uint32_t a2 = Qs2[r0    ][s * 8 + qt + 4];
            uint32_t a3 = Qs2[r0 + 8][s * 8 + qt + 4];
#pragma unroll
            for (int j = 0; j < 8; j++) {
                uint32_t b0 = Ks2[s * 8 + qt    ][j * 8 + qd];
                uint32_t b1 = Ks2[s * 8 + qt + 4][j * 8 + qd];
                mma_bf16(sacc[j], a0, a1, a2, a3, b0, b1);
            }
        }

#pragma unroll
        for (int j = 0; j < 8; j++) {
            float e0 = __expf(sacc[j][0]), e1 = __expf(sacc[j][1]);
            float e2 = __expf(sacc[j][2]), e3 = __expf(sacc[j][3]);
            lsum0 += e0 + e1; lsum1 += e2 + e3;
            PT2[j * 4 + qt][r0]     = pack_bf2(e0, e1);
            PT2[j * 4 + qt][r0 + 8] = pack_bf2(e2, e3);
        }
        __syncwarp();

#pragma unroll
        for (int s = 0; s < 4; s++) {
            uint32_t va[2][4];
#pragma unroll
            for (int rg = 0; rg < 2; rg++) {
                int dr = (rg << 4) + qd;
                va[rg][0] = Vs2[dr    ][s * 8 + qt];
                va[rg][1] = Vs2[dr + 8][s * 8 + qt];
                va[rg][2] = Vs2[dr    ][s * 8 + qt + 4];
                va[rg][3] = Vs2[dr + 8][s * 8 + qt + 4];
            }
#pragma unroll
            for (int j = 0; j < 2; j++) {
                int pcol = (warp << 4) + j * 8 + qd;
                uint32_t b0 = PT2[s * 8 + qt    ][pcol];
                uint32_t b1 = PT2[s * 8 + qt + 4][pcol];
#pragma unroll
                for (int rg = 0; rg < 2; rg++)
                    mma_bf16(oacc[rg][j], va[rg][0], va[rg][1], va[rg][2], va[rg][3], b0, b1);
            }
        }
        __syncthreads();
    }

    lsum0 += __shfl_xor_sync(0xffffffffu, lsum0, 1);
    lsum0 += __shfl_xor_sync(0xffffffffu, lsum0, 2);
    lsum1 += __shfl_xor_sync(0xffffffffu, lsum1, 1);
    lsum1 += __shfl_xor_sync(0xffffffffu, lsum1, 2);
    if (qt == 0) { lsums[r0] = lsum0; lsums[r0 + 8] = lsum1; }
    __syncwarp();

#pragma unroll
    for (int j = 0; j < 2; j++) {
        int p0 = (warp << 4) + j * 8 + (qt << 1);
        float inv0 = 1.0f / lsums[p0];
        float inv1 = 1.0f / lsums[p0 + 1];
#pragma unroll
        for (int rg = 0; rg < 2; rg++) {
            int d = (rg << 4) + qd;
            float v00 = oacc[rg][j][0] * inv0;
            float v10 = oacc[rg][j][1] * inv1;
            float v08 = oacc[rg][j][2] * inv0;
            float v18 = oacc[rg][j][3] * inv1;
            float p00 = __shfl_down_sync(0xffffffffu, v00, 4);
            float p10 = __shfl_down_sync(0xffffffffu, v10, 4);
            float p08 = __shfl_down_sync(0xffffffffu, v08, 4);
            float p18 = __shfl_down_sync(0xffffffffu, v18, 4);
            if ((qd & 1) == 0) {
                int c0 = (h * DH + d) >> 1;
                int c8 = (h * DH + d + 8) >> 1;
                size_t i00 = (size_t)(pb + p0) * 128 + c0;
                size_t i10 = (size_t)(pb + p0 + 1) * 128 + c0;
                size_t i08 = (size_t)(pb + p0) * 128 + c8;
                size_t i18 = (size_t)(pb + p0 + 1) * 128 + c8;
                split2(v00, p00, OH[i00], OL[i00]);
                split2(v10, p10, OH[i10], OL[i10]);
                split2(v08, p08, OH[i08], OL[i08]);
                split2(v18, p18, OH[i18], OL[i18]);
            }
        }
    }
}

// q = LayerNorm(q + resid) * g + b ; also emits packed q
__global__ void add_ln_kernel(float* __restrict__ Qb, const float* __restrict__ R,
                              const float* __restrict__ g, const float* __restrict__ b,
                              uint32_t* __restrict__ QH, uint32_t* __restrict__ QL) {
    const int p = blockIdx.x;
    const int e = threadIdx.x;
    __shared__ float sh[8];
    float x = Qb[(size_t)p * EE + e] + R[(size_t)p * EE + e];
    float s = x;
#pragma unroll
    for (int o = 16; o > 0; o >>= 1) s += __shfl_xor_sync(0xffffffffu, s, o);
    if ((e & 31) == 0) sh[e >> 5] = s;
    __syncthreads();
    float mean = (sh[0] + sh[1] + sh[2] + sh[3] + sh[4] + sh[5] + sh[6] + sh[7]) * (1.0f / 256.0f);
    float d = x - mean;
    __syncthreads();
    s = d * d;
#pragma unroll
    for (int o = 16; o > 0; o >>= 1) s += __shfl_xor_sync(0xffffffffu, s, o);
    if ((e & 31) == 0) sh[e >> 5] = s;
    __syncthreads();
    float var = (sh[0] + sh[1] + sh[2] + sh[3] + sh[4] + sh[5] + sh[6] + sh[7]) * (1.0f / 256.0f);
    float val = d * rsqrtf(var + 1e-5f) * g[e] + b[e];
    Qb[(size_t)p * EE + e] = val;
    float part = __shfl_down_sync(0xffffffffu, val, 1);
    if ((e & 1) == 0) {
        size_t i = (size_t)p * 128 + (e >> 1);
        split2(val, part, QH[i], QL[i]);
    }
}

__global__ void idx_kernel(const float* __restrict__ refs, int* __restrict__ rows,
                           int* __restrict__ cols, float* __restrict__ rfx,
                           float* __restrict__ rfy) {
    int p = blockIdx.x * blockDim.x + threadIdx.x;
    if (p >= PAIRS) return;
    int r = 0, off = 0;
    while (p >= off + (NQ - 1 - r)) { off += NQ - 1 - r; r++; }
    int c = r + 1 + (p - off);
    rows[p] = r; cols[p] = c;
    rfx[p] = 0.5f * (refs[r * 4 + 0] + refs[c * 4 + 0]);
    rfy[p] = 0.5f * (refs[r * 4 + 1] + refs[c * 4 + 1]);
}

__global__ void pairc_kernel(const float* __restrict__ H, const int* __restrict__ rows,
                             const int* __restrict__ cols,
                             uint32_t* __restrict__ PCH, uint32_t* __restrict__ PCL) {
    const int p = blockIdx.x;
    const int e = threadIdx.x;
    int r = rows[p], c = cols[p];
    const float* src = (e < 128) ? (H + (size_t)r * EE + 2 * e)
                                 : (H + (size_t)c * EE + 2 * (e - 128));
    float2 v = *(const float2*)src;
    size_t i = (size_t)p * 256 + e;
    split2(v.x, v.y, PCH[i], PCL[i]);
}

__global__ void addref_kernel(float* __restrict__ Qb, const float* __restrict__ rfx,
                              const float* __restrict__ rfy, const float* __restrict__ Wref,
                              uint32_t* __restrict__ QH, uint32_t* __restrict__ QL) {
    const int p = blockIdx.x;
    const int e = threadIdx.x;
    float val = Qb[(size_t)p * EE + e] + rfx[p] * Wref[e] + rfy[p] * Wref[EE + e];
    Qb[(size_t)p * EE + e] = val;
    float part = __shfl_down_sync(0xffffffffu, val, 1);
    if ((e & 1) == 0) {
        size_t i = (size_t)p * 128 + (e >> 1);
        split2(val, part, QH[i], QL[i]);
    }
}

__global__ void score_kernel(const float* __restrict__ Qb, const float* __restrict__ Tx,
                             const float* __restrict__ lsc, const int* __restrict__ rows,
                             const int* __restrict__ cols, float* __restrict__ out) {
    const int pp = blockIdx.x;
    __shared__ float qr[EE];
    const int tid = threadIdx.x;
    qr[tid] = Qb[(size_t)pp * EE + tid];
    __syncthreads();
    const float scale = expf(lsc[0]);
    const int w = tid >> 5, lane = tid & 31;
    const int r = rows[pp], c = cols[pp];
    for (int t = w; t < TTXT; t += 8) {
        float sum = 0.0f;
#pragma unroll
        for (int i = 0; i < 8; i++)
            sum = fmaf(qr[lane + (i << 5)], Tx[(size_t)t * EE + lane + (i << 5)], sum);
#pragma unroll
        for (int o = 16; o > 0; o >>= 1) sum += __shfl_down_sync(0xffffffffu, sum, o);
        if (lane == 0) {
            float vv = sum * scale;
            out[(size_t)(r * NQ + c) * TTXT + t] = vv;
            out[(size_t)(c * NQ + r) * TTXT + t] = vv;
        }
    }
}

// ----------------------------------- launcher ------------------------------------
extern "C" void kernel_launch(void* const* d_in, const int* in_sizes, int n_in,
                              void* d_out, int out_size) {
    const float* hid    = (const float*)d_in[0];
    const float* memin  = (const float*)d_in[1];
    const float* refs   = (const float*)d_in[2];
    const float* mtext  = (const float*)d_in[3];
    const float* W_pair = (const float*)d_in[6];
    const float* b_pair = (const float*)d_in[7];
    const float* b_mem  = (const float*)d_in[9];
    const float* b_text = (const float*)d_in[11];
    const float* W_ref  = (const float*)d_in[12];
    const float* W_mem  = (const float*)d_in[8];
    const float* W_text = (const float*)d_in[10];
    const float* Wq = (const float*)d_in[13]; const float* bq = (const float*)d_in[14];
    const float* Wk = (const float*)d_in[15]; const float* bk = (const float*)d_in[16];
    const float* Wv = (const float*)d_in[17]; const float* bv = (const float*)d_in[18];
    const float* Wo = (const float*)d_in[19]; const float* bo = (const float*)d_in[20];
    const float* ln1g = (const float*)d_in[21]; const float* ln1b = (const float*)d_in[22];
    const float* ln2g = (const float*)d_in[23]; const float* ln2b = (const float*)d_in[24];
    const float* Wf1 = (const float*)d_in[25]; const float* bf1 = (const float*)d_in[26];
    const float* Wf2 = (const float*)d_in[27]; const float* bf2 = (const float*)d_in[28];
    const float* lsc = (const float*)d_in[29];
    float* out = (float*)d_out;

    float *q, *qh, *kall, *vall, *proj, *text, *rfx, *rfy;
    int *rowp, *colp;
    uint32_t *WpairH, *WpairL, *WmemH, *WmemL, *WtextH, *WtextL;
    uint32_t *WqH, *WqL, *WoH, *WoL, *Wf1H, *Wf1L, *Wf2H, *Wf2L;
    uint32_t *pcH, *pcL, *qPH, *qPL, *minH, *minL, *mtxH, *mtxL;
    uint32_t *memH, *memL, *atH, *atL, *ffH, *ffL;
    cudaGetSymbolAddress((void**)&q,    g_q);
    cudaGetSymbolAddress((void**)&qh,   g_qh);
    cudaGetSymbolAddress((void**)&kall, g_kall);
    cudaGetSymbolAddress((void**)&vall, g_vall);
    cudaGetSymbolAddress((void**)&proj, g_proj);
    cudaGetSymbolAddress((void**)&text, g_text);
    cudaGetSymbolAddress((void**)&rowp, g_rowi);
    cudaGetSymbolAddress((void**)&colp, g_coli);
    cudaGetSymbolAddress((void**)&rfx,  g_refx);
    cudaGetSymbolAddress((void**)&rfy,  g_refy);
    cudaGetSymbolAddress((void**)&WpairH, g_WpairH); cudaGetSymbolAddress((void**)&WpairL, g_WpairL);
    cudaGetSymbolAddress((void**)&WmemH,  g_WmemH);  cudaGetSymbolAddress((void**)&WmemL,  g_WmemL);
    cudaGetSymbolAddress((void**)&WtextH, g_WtextH); cudaGetSymbolAddress((void**)&WtextL, g_WtextL);
    cudaGetSymbolAddress((void**)&WqH, g_WqH); cudaGetSymbolAddress((void**)&WqL, g_WqL);
    cudaGetSymbolAddress((void**)&WoH, g_WoH); cudaGetSymbolAddress((void**)&WoL, g_WoL);
    cudaGetSymbolAddress((void**)&Wf1H, g_Wf1H); cudaGetSymbolAddress((void**)&Wf1L, g_Wf1L);
    cudaGetSymbolAddress((void**)&Wf2H, g_Wf2H); cudaGetSymbolAddress((void**)&Wf2L, g_Wf2L);
    cudaGetSymbolAddress((void**)&pcH, g_pcH);   cudaGetSymbolAddress((void**)&pcL, g_pcL);
    cudaGetSymbolAddress((void**)&qPH, g_qPH);   cudaGetSymbolAddress((void**)&qPL, g_qPL);
    cudaGetSymbolAddress((void**)&minH, g_minH); cudaGetSymbolAddress((void**)&minL, g_minL);
    cudaGetSymbolAddress((void**)&mtxH, g_mtxH); cudaGetSymbolAddress((void**)&mtxL, g_mtxL);
    cudaGetSymbolAddress((void**)&memH, g_memH); cudaGetSymbolAddress((void**)&memL, g_memL);
    cudaGetSymbolAddress((void**)&atH, g_atH);   cudaGetSymbolAddress((void**)&atL, g_atL);
    cudaGetSymbolAddress((void**)&ffH, g_ffH);   cudaGetSymbolAddress((void**)&ffL, g_ffL);

    // ---- single fused pack launch ----
    pack_all<<<(PACK_TOTAL + 255) / 256, 256>>>(W_pair, W_mem, W_text, Wq, Wk, Wv, Wo,
                                                Wf1, Wf2, memin, mtext);

    idx_kernel<<<8, 256>>>(refs, rowp, colp, rfx, rfy);
    pairc_kernel<<<PAIRS, 256>>>(hid, rowp, colp, pcH, pcL);
    gemm_pk<false, false><<<dim3(4, 32), 128>>>(pcH, pcL, WpairH, WpairL, b_pair,
                                                q, nullptr, nullptr, PAIRS, EE, 512);
    addref_kernel<<<PAIRS, 256>>>(q, rfx, rfy, W_ref, qPH, qPL);
    gemm_pk<false, true><<<dim3(4, 64), 128>>>(minH, minL, WmemH, WmemL, b_mem,
                                               nullptr, memH, memL, MMEM, EE, EE);
    gemm_pk<false, false><<<dim3(4, 1), 128>>>(mtxH, mtxL, WtextH, WtextL, b_text,
                                               text, nullptr, nullptr, TTXT, EE, EE);
    gemm_kv_pk<<<dim3(4, 64, 2 * LLAYERS), 128>>>(memH, memL, bk, bv, kall, vall);

    for (int l = 0; l < LLAYERS; l++) {
        gemm_pk<false, false><<<dim3(4, 32), 128>>>(qPH, qPL, WqH + (size_t)l * 32768,
                                                    WqL + (size_t)l * 32768, bq + l * EE,
                                                    qh, nullptr, nullptr, PAIRS, EE, EE);
        flash_bf_kernel<<<dim3(PPAD / 64, HN), 128>>>(qh, kall + (size_t)l * MMEM * EE,
                                                      vall + (size_t)l * MMEM * EE, atH, atL);
        gemm_pk<false, false><<<dim3(4, 32), 128>>>(atH, atL, WoH + (size_t)l * 32768,
                                                    WoL + (size_t)l * 32768, bo + l * EE,
                                                    proj, nullptr, nullptr, PAIRS, EE, EE);
        add_ln_kernel<<<PAIRS, 256>>>(q, proj, ln1g + l * EE, ln1b + l * EE, qPH, qPL);
        gemm_pk<true, true><<<dim3(16, 32), 128>>>(qPH, qPL, Wf1H + (size_t)l * 131072,
                                                   Wf1L + (size_t)l * 131072, bf1 + l * FFD,
                                                   nullptr, ffH, ffL, PAIRS, FFD, EE);
        gemm_pk<false, false><<<dim3(4, 32), 128>>>(ffH, ffL, Wf2H + (size_t)l * 131072,
                                                    Wf2L + (size_t)l * 131072, bf2 + l * EE,
                                                    proj, nullptr, nullptr, PAIRS, EE, FFD);
        add_ln_kernel<<<PAIRS, 256>>>(q, proj, ln2g + l * EE, ln2b + l * EE, qPH, qPL);
    }

    cudaMemsetAsync(d_out, 0, (size_t)out_size * sizeof(float), 0);
    score_kernel<<<PAIRS, 256>>>(q, text, lsc, rowp, colp, out);
}